// round 8
// baseline (speedup 1.0000x reference)
#include <cuda_runtime.h>
#include <cuda_bf16.h>
#include <cstdint>

// Problem constants
#define B_DIM 4
#define S_DIM 256
#define V_DIM 50257
#define D_DIM 768
#define ROWS (B_DIM * S_DIM)     // 1024
#define D4 (D_DIM / 4)           // 192 float4 per output row
#define NTHREADS 256

// ---------------------------------------------------------------------------
// One block per (b,s) row: scan the row's 50257 one_hot floats for its single
// nonzero (hit -> shared memory), __syncthreads, then gather
// out[row][:] = val * weight[col][:] from the same block. No global scratch,
// no second kernel, gathers overlap other rows' scans.
//
// Row starts are misaligned for float4 (50257 % 4 == 1), so: scalar head
// (<=3 elems) + float4 body (8-batched loads for MLP=8) + scalar tail (<=3).
// ---------------------------------------------------------------------------
__device__ __forceinline__ bool nz4(float4 v)
{
    // one_hot values are exactly 0.0f or 1.0f-scale positives; integer OR is exact.
    return ((__float_as_uint(v.x) | __float_as_uint(v.y) |
             __float_as_uint(v.z) | __float_as_uint(v.w)) != 0u);
}

__global__ void __launch_bounds__(NTHREADS)
row_scan_gather_kernel(const float*  __restrict__ oh,
                       const float4* __restrict__ weight,
                       float4*       __restrict__ out)
{
    __shared__ int   s_col;
    __shared__ float s_val;

    const unsigned int row = blockIdx.x;
    const unsigned int tid = threadIdx.x;

    // Flat element range of this row: [a, end). Fits in 32 bits (51.5M total).
    const unsigned int a      = row * (unsigned int)V_DIM;
    const unsigned int end    = a + (unsigned int)V_DIM;
    const unsigned int first4 = (a + 3u) & ~3u;      // first 16B-aligned element
    const unsigned int body_s4 = first4 >> 2;        // float4 index, inclusive
    const unsigned int body_e4 = end >> 2;           // float4 index, exclusive

    // --- scalar head (at most 3 elements; only tids < 3 participate) ---
    if (a + tid < first4) {
        float v = oh[a + tid];
        if (v != 0.0f) { s_col = (int)tid; s_val = v; }
    }
    // --- scalar tail (at most 3 elements) ---
    {
        unsigned int e = (body_e4 << 2) + tid;
        if (e < end) {
            float v = oh[e];
            if (v != 0.0f) { s_col = (int)(e - a); s_val = v; }
        }
    }

    // --- float4 body: batches of 8 independent loads before any test ---
    const float4* __restrict__ oh4 = (const float4*)oh;
    unsigned int i = body_s4 + tid;

    for (; i + 7u * NTHREADS < body_e4; i += 8u * NTHREADS) {
        float4 v[8];
        #pragma unroll
        for (int k = 0; k < 8; ++k)
            v[k] = __ldcs(&oh4[i + (unsigned int)k * NTHREADS]);

        #pragma unroll
        for (int k = 0; k < 8; ++k) {
            if (nz4(v[k])) {
                unsigned int base = (i + (unsigned int)k * NTHREADS) * 4u;
                float vals[4] = {v[k].x, v[k].y, v[k].z, v[k].w};
                #pragma unroll
                for (int l = 0; l < 4; ++l)
                    if (vals[l] != 0.0f) {
                        s_col = (int)(base + (unsigned int)l - a);
                        s_val = vals[l];
                    }
            }
        }
    }
    for (; i < body_e4; i += NTHREADS) {
        float4 v = __ldcs(&oh4[i]);
        if (nz4(v)) {
            unsigned int base = i * 4u;
            float vals[4] = {v.x, v.y, v.z, v.w};
            #pragma unroll
            for (int l = 0; l < 4; ++l)
                if (vals[l] != 0.0f) {
                    s_col = (int)(base + (unsigned int)l - a);
                    s_val = vals[l];
                }
        }
    }

    __syncthreads();

    // --- gather: out[row][:] = s_val * weight[s_col][:] ---
    const int   col = s_col;
    const float s   = s_val;
    if (tid < D4) {
        float4 w = __ldg(&weight[(size_t)col * D4 + tid]);
        float4 o;
        o.x = s * w.x;
        o.y = s * w.y;
        o.z = s * w.z;
        o.w = s * w.w;
        out[(size_t)row * D4 + tid] = o;
    }
}

// ---------------------------------------------------------------------------
// Launch: d_in[0] = one_hot [B,S,V] f32, d_in[1] = weight [V,D] f32.
// Output [B,S,D] f32. Single kernel, one block per row.
// ---------------------------------------------------------------------------
extern "C" void kernel_launch(void* const* d_in, const int* in_sizes, int n_in,
                              void* d_out, int out_size)
{
    const float*  oh     = (const float*)d_in[0];
    const float4* weight = (const float4*)d_in[1];
    float4*       out    = (float4*)d_out;

    (void)in_sizes; (void)n_in; (void)out_size;

    row_scan_gather_kernel<<<ROWS, NTHREADS>>>(oh, weight, out);
}

// round 9
// speedup vs baseline: 1.5106x; 1.5106x over previous
#include <cuda_runtime.h>
#include <cuda_bf16.h>
#include <cstdint>

// Problem constants
#define B_DIM 4
#define S_DIM 256
#define V_DIM 50257
#define D_DIM 768
#define ROWS (B_DIM * S_DIM)     // 1024
#define D4 (D_DIM / 4)           // 192 float4 per output row
#define NTHREADS 256
#define BATCH 8                  // float4 loads batched per thread per chunk

// ---------------------------------------------------------------------------
// One block per (b,s) row, with EARLY EXIT: the row has exactly one nonzero
// at a uniform-random column. Scan linearly in chunks of 256*8 float4
// (8192 elems); once any thread records the hit in shared memory it raises a
// flag and the whole block stops scanning (expected ~58% of row read).
// Then the same block gathers out[row][:] = val * weight[col][:].
//
// Row stride 50257 % 4 == 1, so: scalar head (<=3) + float4 body + scalar
// tail (<=3), head/tail checked upfront.
// ---------------------------------------------------------------------------
__device__ __forceinline__ bool nz4(float4 v)
{
    return ((__float_as_uint(v.x) | __float_as_uint(v.y) |
             __float_as_uint(v.z) | __float_as_uint(v.w)) != 0u);
}

__global__ void __launch_bounds__(NTHREADS)
row_scan_gather_ee_kernel(const float*  __restrict__ oh,
                          const float4* __restrict__ weight,
                          float4*       __restrict__ out)
{
    __shared__ int   s_col;
    __shared__ float s_val;
    __shared__ int   s_found;

    const unsigned int row = blockIdx.x;
    const unsigned int tid = threadIdx.x;

    if (tid == 0) s_found = 0;
    __syncthreads();

    // Flat element range of this row: [a, end). 51.5M total fits in 32 bits.
    const unsigned int a       = row * (unsigned int)V_DIM;
    const unsigned int end     = a + (unsigned int)V_DIM;
    const unsigned int first4  = (a + 3u) & ~3u;   // first 16B-aligned element
    const unsigned int body_s4 = first4 >> 2;      // float4 index, inclusive
    const unsigned int body_e4 = end >> 2;         // float4 index, exclusive

    // --- scalar head (<=3 elems) ---
    if (a + tid < first4) {
        float v = oh[a + tid];
        if (v != 0.0f) {
            s_col = (int)tid; s_val = v;
            __threadfence_block();
            s_found = 1;
        }
    }
    // --- scalar tail (<=3 elems) ---
    {
        unsigned int e = (body_e4 << 2) + tid;
        if (e < end) {
            float v = oh[e];
            if (v != 0.0f) {
                s_col = (int)(e - a); s_val = v;
                __threadfence_block();
                s_found = 1;
            }
        }
    }

    // --- float4 body with early exit ---
    const float4* __restrict__ oh4 = (const float4*)oh;
    volatile int* vfound = &s_found;
    unsigned int i = body_s4 + tid;

    for (; i + (BATCH - 1u) * NTHREADS < body_e4; i += BATCH * NTHREADS) {
        if (*vfound) break;                       // uniform branch: whole block exits

        float4 v[BATCH];
        #pragma unroll
        for (int k = 0; k < BATCH; ++k)
            v[k] = __ldcs(&oh4[i + (unsigned int)k * NTHREADS]);

        #pragma unroll
        for (int k = 0; k < BATCH; ++k) {
            if (nz4(v[k])) {
                unsigned int base = (i + (unsigned int)k * NTHREADS) * 4u;
                float vals[4] = {v[k].x, v[k].y, v[k].z, v[k].w};
                #pragma unroll
                for (int l = 0; l < 4; ++l)
                    if (vals[l] != 0.0f) {
                        s_col = (int)(base + (unsigned int)l - a);
                        s_val = vals[l];
                    }
                __threadfence_block();
                s_found = 1;
            }
        }
    }
    // remainder of the body (only if not found yet)
    if (!*vfound) {
        for (; i < body_e4; i += NTHREADS) {
            float4 v = __ldcs(&oh4[i]);
            if (nz4(v)) {
                unsigned int base = i * 4u;
                float vals[4] = {v.x, v.y, v.z, v.w};
                #pragma unroll
                for (int l = 0; l < 4; ++l)
                    if (vals[l] != 0.0f) {
                        s_col = (int)(base + (unsigned int)l - a);
                        s_val = vals[l];
                    }
                __threadfence_block();
                s_found = 1;
            }
        }
    }

    __syncthreads();   // s_col / s_val now safely visible

    // --- gather: out[row][:] = s_val * weight[s_col][:] ---
    const int   col = s_col;
    const float s   = s_val;
    if (tid < D4) {
        float4 w = __ldg(&weight[(size_t)col * D4 + tid]);
        float4 o;
        o.x = s * w.x;
        o.y = s * w.y;
        o.z = s * w.z;
        o.w = s * w.w;
        out[(size_t)row * D4 + tid] = o;
    }
}

// ---------------------------------------------------------------------------
// Launch: d_in[0] = one_hot [B,S,V] f32, d_in[1] = weight [V,D] f32.
// Output [B,S,D] f32. Single kernel, one block per row, early exit.
// ---------------------------------------------------------------------------
extern "C" void kernel_launch(void* const* d_in, const int* in_sizes, int n_in,
                              void* d_out, int out_size)
{
    const float*  oh     = (const float*)d_in[0];
    const float4* weight = (const float4*)d_in[1];
    float4*       out    = (float4*)d_out;

    (void)in_sizes; (void)n_in; (void)out_size;

    row_scan_gather_ee_kernel<<<ROWS, NTHREADS>>>(oh, weight, out);
}

// round 10
// speedup vs baseline: 1.5305x; 1.0131x over previous
#include <cuda_runtime.h>
#include <cuda_bf16.h>
#include <cstdint>

// Problem constants
#define B_DIM 4
#define S_DIM 256
#define V_DIM 50257
#define D_DIM 768
#define ROWS (B_DIM * S_DIM)     // 1024
#define D4 (D_DIM / 4)           // 192 float4 per output row
#define NTHREADS 256
#define BATCH 2                  // float4 loads per thread per chunk (8KB chunk)

// ---------------------------------------------------------------------------
// One block per (b,s) row with fine-grained early exit. Chunk = 256 thr x 2
// float4 = 8KB; the shared found-flag is read BEFORE the chunk's loads issue
// (LDS latency hides under LDG), so flag polling costs nothing and over-scan
// is ~1.5 chunks/row. Expected traffic ~115MB (vs 206MB full scan).
// The finder records (col,val) in shared; after __syncthreads the block
// gathers out[row][:] = val * weight[col][:].
//
// Row stride 50257 % 4 == 1: scalar head (<=3) + float4 body + scalar tail.
// ---------------------------------------------------------------------------
__device__ __forceinline__ bool nz4(float4 v)
{
    return ((__float_as_uint(v.x) | __float_as_uint(v.y) |
             __float_as_uint(v.z) | __float_as_uint(v.w)) != 0u);
}

__global__ void __launch_bounds__(NTHREADS)
row_scan_gather_ee2_kernel(const float*  __restrict__ oh,
                           const float4* __restrict__ weight,
                           float4*       __restrict__ out)
{
    __shared__ int   s_col;
    __shared__ float s_val;
    __shared__ int   s_found;

    const unsigned int row = blockIdx.x;
    const unsigned int tid = threadIdx.x;

    if (tid == 0) s_found = 0;
    __syncthreads();

    // Flat element range of this row: [a, end). 51.5M total fits in 32 bits.
    const unsigned int a       = row * (unsigned int)V_DIM;
    const unsigned int end     = a + (unsigned int)V_DIM;
    const unsigned int first4  = (a + 3u) & ~3u;   // first 16B-aligned element
    const unsigned int body_s4 = first4 >> 2;      // float4 index, inclusive
    const unsigned int body_e4 = end >> 2;         // float4 index, exclusive

    // --- scalar head (<=3 elems) ---
    if (a + tid < first4) {
        float v = oh[a + tid];
        if (v != 0.0f) {
            s_col = (int)tid; s_val = v;
            __threadfence_block();
            s_found = 1;
        }
    }
    // --- scalar tail (<=3 elems) ---
    {
        unsigned int e = (body_e4 << 2) + tid;
        if (e < end) {
            float v = oh[e];
            if (v != 0.0f) {
                s_col = (int)(e - a); s_val = v;
                __threadfence_block();
                s_found = 1;
            }
        }
    }

    // --- float4 body: 8KB chunks, flag read issued before the chunk's LDGs ---
    const float4* __restrict__ oh4 = (const float4*)oh;
    volatile int* vfound = &s_found;
    unsigned int i = body_s4 + tid;

    for (; i + NTHREADS < body_e4; i += BATCH * NTHREADS) {
        int f = *vfound;                       // LDS: resolves under the LDGs
        float4 v0 = __ldcs(&oh4[i]);
        float4 v1 = __ldcs(&oh4[i + NTHREADS]);
        if (f) break;                          // hit found elsewhere: our data is zeros

        if (nz4(v0)) {
            unsigned int base = i * 4u;
            float vals[4] = {v0.x, v0.y, v0.z, v0.w};
            #pragma unroll
            for (int l = 0; l < 4; ++l)
                if (vals[l] != 0.0f) { s_col = (int)(base + (unsigned int)l - a); s_val = vals[l]; }
            __threadfence_block();
            s_found = 1;
        }
        if (nz4(v1)) {
            unsigned int base = (i + NTHREADS) * 4u;
            float vals[4] = {v1.x, v1.y, v1.z, v1.w};
            #pragma unroll
            for (int l = 0; l < 4; ++l)
                if (vals[l] != 0.0f) { s_col = (int)(base + (unsigned int)l - a); s_val = vals[l]; }
            __threadfence_block();
            s_found = 1;
        }
    }
    // remainder (last partial chunk), only if not yet found
    if (!*vfound) {
        for (; i < body_e4; i += NTHREADS) {
            float4 v = __ldcs(&oh4[i]);
            if (nz4(v)) {
                unsigned int base = i * 4u;
                float vals[4] = {v.x, v.y, v.z, v.w};
                #pragma unroll
                for (int l = 0; l < 4; ++l)
                    if (vals[l] != 0.0f) { s_col = (int)(base + (unsigned int)l - a); s_val = vals[l]; }
                __threadfence_block();
                s_found = 1;
            }
        }
    }

    __syncthreads();   // s_col / s_val now safely visible

    // --- gather: out[row][:] = s_val * weight[s_col][:] ---
    const int   col = s_col;
    const float s   = s_val;
    if (tid < D4) {
        float4 w = __ldg(&weight[(size_t)col * D4 + tid]);
        float4 o;
        o.x = s * w.x;
        o.y = s * w.y;
        o.z = s * w.z;
        o.w = s * w.w;
        out[(size_t)row * D4 + tid] = o;
    }
}

// ---------------------------------------------------------------------------
// Launch: d_in[0] = one_hot [B,S,V] f32, d_in[1] = weight [V,D] f32.
// Output [B,S,D] f32. Single kernel, one block per row, fine-grained exit.
// ---------------------------------------------------------------------------
extern "C" void kernel_launch(void* const* d_in, const int* in_sizes, int n_in,
                              void* d_out, int out_size)
{
    const float*  oh     = (const float*)d_in[0];
    const float4* weight = (const float4*)d_in[1];
    float4*       out    = (float4*)d_out;

    (void)in_sizes; (void)n_in; (void)out_size;

    row_scan_gather_ee2_kernel<<<ROWS, NTHREADS>>>(oh, weight, out);
}